// round 7
// baseline (speedup 1.0000x reference)
#include <cuda_runtime.h>
#include <cuda_bf16.h>
#include <cstddef>

// Enframe: x (8,2,480000) f32 -> out (8,4096,934) f32
//   out[b, c*2048 + k, t] = x[b, c, t*512 + k];  k = q*512 + r, bc = b*2+c:
//   out[bc, q*512 + r, t] = x[bc, (t+q)*512 + r]
// Block = 8 r-columns x ALL 937 slots (one transpose stripe in smem).
// The same 8-r stripe serves all 4 q shifts -> block writes 32 complete
// output rows as full-length contiguous streams (perfectly coalesced,
// partial sectors only at row ends). Input read exactly once, one aligned
// 32B sector per (slot, block). 1024 blocks = single wave at 7 blocks/SM.

#define S_LEN    480000
#define T_OUT    934          // (480000 - 2048)/512 + 1
#define SLOTS    937          // max slot = 933 + 3 = 936
#define ROWS     2048         // per-bc output rows
#define R_TILE   8
#define R_STRIDE 940          // floats per smem row; 940 % 32 = 12 -> STS conflict-free

__global__ __launch_bounds__(256, 7) void enframe_kernel(const float2* __restrict__ x2,
                                                         float* __restrict__ out) {
    __shared__ float trans[R_TILE * R_STRIDE];   // 8 * 940 * 4 = 30080 B

    const int rt  = blockIdx.x;    // 0..63   rbase = rt*8
    const int bc  = blockIdx.y;    // 0..15
    const int tid = threadIdx.x;   // 0..255
    const int rbase = rt * R_TILE;

    // ---- Load phase: trans[rl][s] = x[bc, s*512 + rbase + rl] ----
    // Thread loads float2 (2 r's) of one slot; 4 threads cover a block's 32B
    // sector of a slot; 64 slots per pass; 15 passes cover 937 slots.
    const int rp   = tid & 3;      // r pair: rl = 2*rp, 2*rp+1
    const int soff = tid >> 2;     // 0..63
    const float2* __restrict__ xin =
        x2 + (size_t)bc * (S_LEN / 2) + (rbase >> 1) + rp;

    float2 v[5];
#pragma unroll
    for (int b = 0; b < 3; ++b) {
#pragma unroll
        for (int p = 0; p < 5; ++p) {
            const int s = (b * 5 + p) * 64 + soff;
            v[p] = make_float2(0.f, 0.f);
            if (s < SLOTS) v[p] = xin[(size_t)s * 256];
        }
#pragma unroll
        for (int p = 0; p < 5; ++p) {
            const int s = (b * 5 + p) * 64 + soff;
            if (s < SLOTS) {
                trans[(2 * rp) * R_STRIDE + s]     = v[p].x;   // conflict-free
                trans[(2 * rp + 1) * R_STRIDE + s] = v[p].y;   // conflict-free
            }
        }
    }
    __syncthreads();

    // ---- Store phase: warp w -> (q = w>>1, r half = w&1), 4 rows per warp ----
    // out row (q, rbase+rl) [934 floats contiguous] = trans[rl][q .. q+933]
    const int w    = tid >> 5;
    const int lane = tid & 31;
    const int q    = w >> 1;
    const int r0   = (w & 1) * 4;

    float* __restrict__ outb = out + (size_t)bc * ROWS * T_OUT;

#pragma unroll
    for (int j = 0; j < 4; ++j) {
        const int rl = r0 + j;
        const float* __restrict__ src = &trans[rl * R_STRIDE + q];
        float* __restrict__ o = outb + (size_t)(q * 512 + rbase + rl) * T_OUT;
#pragma unroll
        for (int i = 0; i < 29; ++i) {              // 29*32 = 928 t
            o[i * 32 + lane] = src[i * 32 + lane];  // LDS stride-1 + STG 128B coalesced
        }
        const int t = 928 + lane;                   // tail: 6 lanes
        if (t < T_OUT) o[t] = src[t];
    }
}

extern "C" void kernel_launch(void* const* d_in, const int* in_sizes, int n_in,
                              void* d_out, int out_size) {
    const float2* x = (const float2*)d_in[0];
    float* out = (float*)d_out;

    dim3 block(256, 1, 1);
    dim3 grid(64, 16, 1);   // (r stripes of 8, bc)
    enframe_kernel<<<grid, block>>>(x, out);
}

// round 8
// speedup vs baseline: 1.3425x; 1.3425x over previous
#include <cuda_runtime.h>
#include <cuda_bf16.h>
#include <cstddef>

// Enframe: x (8,2,480000) f32 -> out (8,4096,934) f32
//   out[b, c*2048 + k, t] = x[b, c, t*512 + k]
// Decompose k = 512*q + r (q in [0,4), r in [0,512)), bc = b*2+c:
//   out[bc, q*512 + r, t] = x[bc, (t+q)*512 + r]
// R3 structure (best measured): tile 128 t x 32 r, grid 16x8x16 = 2048 blocks.
// Changes vs R3: (1) load phase batches all 5 LDG.128 into registers before
// any STS (MLP=5 hides DRAM latency), (2) __stcs evict-first output stores.

#define S_LEN     480000
#define T_OUT     934          // (480000 - 2048)/512 + 1
#define SLOTS     937          // max slot = 933 + 3 = 936
#define ROWS      2048         // per-bc output rows
#define R_PAD     33
#define T_TILE    128
#define SLOT_NEED 131          // 128 t + q shift (3)

__global__ __launch_bounds__(256) void enframe_kernel(const float4* __restrict__ x4,
                                                      float* __restrict__ out) {
    __shared__ float tile[SLOT_NEED * R_PAD];   // 131*33*4 = 17292 B

    const int rt = blockIdx.x;   // 0..15  r base = rt*32
    const int tt = blockIdx.y;   // 0..7   t base = tt*128
    const int bc = blockIdx.z;   // 0..15
    const int tx = threadIdx.x;  // 0..31
    const int ty = threadIdx.y;  // 0..7

    const int tb = tt * T_TILE;
    const float4* __restrict__ xin = x4 + (size_t)bc * (S_LEN / 4);

    const bool interior = (tt < 7);     // t-tiles 0..6: no guards anywhere

    // ---- Load phase: issue all 5 LDG.128 first (MLP=5), then STS ----
    const int c      = tx & 7;          // float4 column: r = rt*32 + 4c + j
    const int rowoff = tx >> 3;         // 0..3
    const int lrow   = ty * 4 + rowoff; // 0..31

    float4 v[5];
#pragma unroll
    for (int p = 0; p < 5; ++p) {
        const int row = p * 32 + lrow;
        v[p] = make_float4(0.f, 0.f, 0.f, 0.f);
        if (row < SLOT_NEED) {
            const int s = tb + row;
            if (interior || s < SLOTS) v[p] = xin[(size_t)s * 128 + rt * 8 + c];
        }
    }
#pragma unroll
    for (int p = 0; p < 5; ++p) {
        const int row = p * 32 + lrow;
        if (row < SLOT_NEED) {
            float* dst = &tile[row * R_PAD + 4 * c];   // conflict-free STS
            dst[0] = v[p].x; dst[1] = v[p].y; dst[2] = v[p].z; dst[3] = v[p].w;
        }
    }
    __syncthreads();

    // ---- Store phase: warp ty -> (q = ty>>1, half = ty&1); lane = t pair ----
    const int q    = ty >> 1;
    const int half = ty & 1;
    const int t    = tb + half * 64 + 2 * tx;      // even t; pair (t, t+1)
    const int row  = half * 64 + 2 * tx + q;       // slot row for t (row+1 -> t+1)
    const float* __restrict__ src = &tile[row * R_PAD];

    float* __restrict__ o = out + (size_t)bc * ROWS * T_OUT
                                + (size_t)(q * 512 + rt * 32) * T_OUT + t;

    if (interior || t < T_OUT) {     // t even, T_OUT even -> pair fully valid
#pragma unroll
        for (int rl = 0; rl < 32; ++rl) {
            float2 w;
            w.x = src[rl];            // tile[row][rl]
            w.y = src[R_PAD + rl];    // tile[row+1][rl]  (slot s+1 -> t+1)
            __stcs((float2*)o, w);    // STG.64 evict-first, 8B-aligned
            o += T_OUT;
        }
    }
}

extern "C" void kernel_launch(void* const* d_in, const int* in_sizes, int n_in,
                              void* d_out, int out_size) {
    const float4* x = (const float4*)d_in[0];
    float* out = (float*)d_out;

    dim3 block(32, 8, 1);
    dim3 grid(16, 8, 16);   // (r tiles of 32, t tiles of 128, bc)
    enframe_kernel<<<grid, block>>>(x, out);
}